// round 9
// baseline (speedup 1.0000x reference)
#include <cuda_runtime.h>
#include <cuda_bf16.h>
#include <cstdint>

// LocallyConnected1d: out[b,c,o] = (1/8) * sum_{i<64,k<8} x[b,i,4o+k] * w[c,i,o,k]
// x: [128, 64, 1028] fp32, w: [1, 64, 64, 256, 8] fp32, out: [128, 64, 256] fp32
//
// Per o: GEMM M=128(b), N=64(c), K=512 via mma.sync m16n8k8 tf32 (single pass).
// Proven load path: LDG float4 prefetch -> cvt.rna.tf32 -> STS.128 into
// double-buffered SMEM (tf32 stored as u32), one __syncthreads per chunk.

#define CINC  64
#define NCOUT 64
#define OD    256
#define LL    1028

#define KC      64              // K per chunk (64 tf32 = 256 B rows)
#define NCHUNK  8               // 512 / 64

// per-stage: A[128][64]u32 = 32 KB | B[64][64]u32 = 16 KB
#define A_OFF  0
#define B_OFF  32768
#define STAGE_SIZE 49152
#define SMEM_BYTES (2 * STAGE_SIZE)   // 96 KB dynamic

// swizzle for 256-byte rows: XOR byte-bits [6:4] with row%8 (addr bits [10:8])
#define SWZ(off) ((uint32_t)(off) ^ ((((uint32_t)(off)) >> 4) & 0x70u))

static __device__ __forceinline__ uint32_t smem_u32(const void* p) {
    uint32_t a;
    asm("{ .reg .u64 t; cvta.to.shared.u64 t, %1; cvt.u32.u64 %0, t; }"
        : "=r"(a) : "l"(p));
    return a;
}

static __device__ __forceinline__ uint32_t f2tf32(float f) {
    uint32_t r;
    asm("cvt.rna.tf32.f32 %0, %1;" : "=r"(r) : "f"(f));
    return r;
}

#define LDSM_X4(r, addr)                                                     \
    asm volatile("ldmatrix.sync.aligned.m8n8.x4.shared.b16 {%0,%1,%2,%3}, [%4];" \
        : "=r"((r)[0]), "=r"((r)[1]), "=r"((r)[2]), "=r"((r)[3]) : "r"(addr))

#define MMA_TF32(c, a, b0, b1)                                               \
    asm volatile("mma.sync.aligned.m16n8k8.row.col.f32.tf32.tf32.f32 "       \
        "{%0,%1,%2,%3}, {%4,%5,%6,%7}, {%8,%9}, {%0,%1,%2,%3};"              \
        : "+f"((c)[0]), "+f"((c)[1]), "+f"((c)[2]), "+f"((c)[3])             \
        : "r"((a)[0]), "r"((a)[1]), "r"((a)[2]), "r"((a)[3]),                \
          "r"(b0), "r"(b1))

// 8 f32 -> 8 tf32(u32), stored as two 16B groups at SWZ(off) / SWZ(off+16)
static __device__ __forceinline__ void cvt_tf32_store(
    float4 v0, float4 v1, char* stgp, uint32_t region, uint32_t off)
{
    uint4 t0, t1;
    t0.x = f2tf32(v0.x);  t0.y = f2tf32(v0.y);
    t0.z = f2tf32(v0.z);  t0.w = f2tf32(v0.w);
    t1.x = f2tf32(v1.x);  t1.y = f2tf32(v1.y);
    t1.z = f2tf32(v1.z);  t1.w = f2tf32(v1.w);
    *reinterpret_cast<uint4*>(stgp + region + SWZ(off))      = t0;
    *reinterpret_cast<uint4*>(stgp + region + SWZ(off + 16)) = t1;
}

__global__ __launch_bounds__(256, 2)
void lc1d_tf32_kernel(const float* __restrict__ x,
                      const float* __restrict__ w,
                      float* __restrict__ out)
{
    extern __shared__ char smem[];
    const uint32_t sb = smem_u32(smem);

    const int o   = blockIdx.x;
    const int tid = threadIdx.x;
    const int wid = tid >> 5;
    const int lid = tid & 31;

    // warp tile: 32(m=b) x 32(n=c); warp grid 4m x 2n
    const int m_base = (wid & 3) * 32;
    const int n_base = (wid >> 2) * 32;

    float acc[2][4][4];
    #pragma unroll
    for (int mt = 0; mt < 2; mt++)
        #pragma unroll
        for (int nt = 0; nt < 4; nt++)
            #pragma unroll
            for (int r = 0; r < 4; r++)
                acc[mt][nt][r] = 0.0f;

    // prefetch registers
    float4 xr[4][2];
    float4 wr[2][2];

    // gather decomposition
    const int xb   = tid & 127;        // b row for X
    const int xii0 = tid >> 7;         // 0..1, +2 per it (4 its -> iw 0..7)
    const int wc   = tid & 63;         // c row for W
    const int wii0 = tid >> 6;         // 0..3, +4 per it (2 its -> iw 0..7)

    const float* xbase = x + (size_t)xb * CINC * LL + (size_t)o * 4;
    const float* wbase = w + (size_t)wc * CINC * (OD * 8) + (size_t)o * 8;

    // ---- prefetch chunk 0 ----
    #pragma unroll
    for (int it = 0; it < 4; it++) {
        const float* src = xbase + (size_t)(xii0 + it * 2) * LL;
        xr[it][0] = *reinterpret_cast<const float4*>(src);
        xr[it][1] = *reinterpret_cast<const float4*>(src + 4);
    }
    #pragma unroll
    for (int it = 0; it < 2; it++) {
        const float4* src = reinterpret_cast<const float4*>(
            wbase + (size_t)(wii0 + it * 4) * (OD * 8));
        wr[it][0] = __ldcs(src + 0);
        wr[it][1] = __ldcs(src + 1);
    }

    for (int j = 0; j < NCHUNK; j++) {
        const uint32_t stg = (uint32_t)(j & 1) * STAGE_SIZE;
        char* stgp = smem + stg;

        // ---- convert prefetched chunk j -> smem stage (tf32) ----
        #pragma unroll
        for (int it = 0; it < 4; it++) {
            int iw = xii0 + it * 2;
            cvt_tf32_store(xr[it][0], xr[it][1], stgp, A_OFF,
                           (uint32_t)(xb * 256 + iw * 32));
        }
        #pragma unroll
        for (int it = 0; it < 2; it++) {
            int iw = wii0 + it * 4;
            cvt_tf32_store(wr[it][0], wr[it][1], stgp, B_OFF,
                           (uint32_t)(wc * 256 + iw * 32));
        }
        __syncthreads();   // single barrier per chunk (double buffer)

        // ---- issue global prefetch for chunk j+1 (hides under MMA) ----
        if (j + 1 < NCHUNK) {
            const int ibase = (j + 1) * 8;
            #pragma unroll
            for (int it = 0; it < 4; it++) {
                const float* src = xbase + (size_t)(ibase + xii0 + it * 2) * LL;
                xr[it][0] = *reinterpret_cast<const float4*>(src);
                xr[it][1] = *reinterpret_cast<const float4*>(src + 4);
            }
            #pragma unroll
            for (int it = 0; it < 2; it++) {
                const float4* src = reinterpret_cast<const float4*>(
                    wbase + (size_t)(ibase + wii0 + it * 4) * (OD * 8));
                wr[it][0] = __ldcs(src + 0);
                wr[it][1] = __ldcs(src + 1);
            }
        }

        // ---- MMA over 8 k8-steps of this chunk ----
        const uint32_t sstg = sb + stg;
        #pragma unroll
        for (int kk = 0; kk < 8; kk++) {
            uint32_t a[2][4], b[2][4];

            #pragma unroll
            for (int mt = 0; mt < 2; mt++) {
                uint32_t row = (uint32_t)(m_base + mt * 16 + (lid & 15));
                uint32_t off = SWZ(row * 256 + (uint32_t)kk * 32
                                   + (uint32_t)(lid >> 4) * 16);
                LDSM_X4(a[mt], sstg + A_OFF + off);
            }
            #pragma unroll
            for (int nt2 = 0; nt2 < 2; nt2++) {
                uint32_t row = (uint32_t)(n_base + nt2 * 16 + (lid & 15));
                uint32_t off = SWZ(row * 256 + (uint32_t)kk * 32
                                   + (uint32_t)(lid >> 4) * 16);
                LDSM_X4(b[nt2], sstg + B_OFF + off);
            }

            #pragma unroll
            for (int mt = 0; mt < 2; mt++) {
                #pragma unroll
                for (int nt = 0; nt < 4; nt++) {
                    const int nt2 = nt >> 1;
                    const int sel = nt & 1;
                    MMA_TF32(acc[mt][nt], a[mt],
                             b[nt2][sel], b[nt2][sel + 2]);
                }
            }
        }
        // no trailing sync: next convert targets the other stage; the single
        // sync above guarantees all reads of that stage (chunk j-1) are done.
    }

    // ---- epilogue: scale by 1/sqrt(64)=0.125, scatter ----
    const float scale = 0.125f;
    const int r    = lid >> 2;
    const int col2 = (lid & 3) * 2;
    #pragma unroll
    for (int mt = 0; mt < 2; mt++) {
        #pragma unroll
        for (int nt = 0; nt < 4; nt++) {
            int b0 = m_base + mt * 16 + r;
            int n0 = n_base + nt * 8 + col2;
            out[((size_t)b0 * NCOUT + n0) * OD + o]           = acc[mt][nt][0] * scale;
            out[((size_t)b0 * NCOUT + n0 + 1) * OD + o]       = acc[mt][nt][1] * scale;
            out[((size_t)(b0 + 8) * NCOUT + n0) * OD + o]     = acc[mt][nt][2] * scale;
            out[((size_t)(b0 + 8) * NCOUT + n0 + 1) * OD + o] = acc[mt][nt][3] * scale;
        }
    }
}

extern "C" void kernel_launch(void* const* d_in, const int* in_sizes, int n_in,
                              void* d_out, int out_size) {
    const float* x = (const float*)d_in[0];
    const float* w = (const float*)d_in[1];
    float* out = (float*)d_out;

    static int configured = 0;
    if (!configured) {
        cudaFuncSetAttribute(lc1d_tf32_kernel,
                             cudaFuncAttributeMaxDynamicSharedMemorySize, SMEM_BYTES);
        configured = 1;
    }
    lc1d_tf32_kernel<<<OD, 256, SMEM_BYTES>>>(x, w, out);
}

// round 10
// speedup vs baseline: 1.2176x; 1.2176x over previous
#include <cuda_runtime.h>
#include <cuda_bf16.h>
#include <cstdint>

// LocallyConnected1d: out[b,c,o] = (1/8) * sum_{i<64,k<8} x[b,i,4o+k] * w[c,i,o,k]
// x: [128, 64, 1028] fp32, w: [1, 64, 64, 256, 8] fp32, out: [128, 64, 256] fp32
//
// Grid (256 o, 2 m-halves): each block = GEMM M=64(b), N=64(c), K=512 via
// mma.sync m16n8k8 tf32. KC=32 chunks, 2-stage 32KB SMEM, 4 CTAs/SM target.
// Pair-lane gather: 2 lanes share one 32B strip -> 16 lines per LDG.128.

#define CINC  64
#define NCOUT 64
#define OD    256
#define LL    1028
#define M_BLK 64

#define KC      32              // K per chunk (32 tf32 = 128 B rows, SW128)
#define NCHUNK  16              // 512 / 32

// per-stage: A[64][32]u32 = 8 KB | B[64][32]u32 = 8 KB
#define A_OFF  0
#define B_OFF  8192
#define STAGE_SIZE 16384
#define SMEM_BYTES (2 * STAGE_SIZE)   // 32 KB static

// SW128 swizzle for 128-byte rows (proven in R6/R7)
#define SWZ(off) ((uint32_t)(off) ^ ((((uint32_t)(off)) >> 3) & 0x70u))

static __device__ __forceinline__ uint32_t smem_u32(const void* p) {
    uint32_t a;
    asm("{ .reg .u64 t; cvta.to.shared.u64 t, %1; cvt.u32.u64 %0, t; }"
        : "=r"(a) : "l"(p));
    return a;
}

static __device__ __forceinline__ uint32_t f2tf32(float f) {
    uint32_t r;
    asm("cvt.rna.tf32.f32 %0, %1;" : "=r"(r) : "f"(f));
    return r;
}

#define LDSM_X4(r, addr)                                                     \
    asm volatile("ldmatrix.sync.aligned.m8n8.x4.shared.b16 {%0,%1,%2,%3}, [%4];" \
        : "=r"((r)[0]), "=r"((r)[1]), "=r"((r)[2]), "=r"((r)[3]) : "r"(addr))

#define MMA_TF32(c, a, b0, b1)                                               \
    asm volatile("mma.sync.aligned.m16n8k8.row.col.f32.tf32.tf32.f32 "       \
        "{%0,%1,%2,%3}, {%4,%5,%6,%7}, {%8,%9}, {%0,%1,%2,%3};"              \
        : "+f"((c)[0]), "+f"((c)[1]), "+f"((c)[2]), "+f"((c)[3])             \
        : "r"((a)[0]), "r"((a)[1]), "r"((a)[2]), "r"((a)[3]),                \
          "r"(b0), "r"(b1))

// 4 f32 -> 4 tf32, one STS.128
static __device__ __forceinline__ void cvt_sts(float4 v, char* dst) {
    uint4 t;
    t.x = f2tf32(v.x);  t.y = f2tf32(v.y);
    t.z = f2tf32(v.z);  t.w = f2tf32(v.w);
    *reinterpret_cast<uint4*>(dst) = t;
}

__global__ __launch_bounds__(256, 4)
void lc1d_tf32_kernel(const float* __restrict__ x,
                      const float* __restrict__ w,
                      float* __restrict__ out)
{
    __shared__ char smem[SMEM_BYTES];
    const uint32_t sb = smem_u32(smem);

    const int o     = blockIdx.x;
    const int bbase = blockIdx.y * M_BLK;
    const int tid   = threadIdx.x;
    const int wid   = tid >> 5;
    const int lid   = tid & 31;

    // warp tile: 16(m=b) x 32(n=c); warp grid 4m x 2n
    const int m_base = (wid & 3) * 16;
    const int n_base = (wid >> 2) * 32;

    float acc[4][4];
    #pragma unroll
    for (int nt = 0; nt < 4; nt++)
        #pragma unroll
        for (int r = 0; r < 4; r++)
            acc[nt][r] = 0.0f;

    // pair-lane strip decomposition: pair p covers strip (row, i), halves h
    const int p  = tid >> 1;
    const int h  = tid & 1;
    const int si = p & 3;            // i-row within chunk (0..3)
    const int sr = (p >> 2) & 31;    // row 0..31; second strip at +32

    // per-thread gmem bases (strip starts, + h*16B)
    const float* xbase = x + ((size_t)(bbase + sr) * CINC + si) * LL
                           + (size_t)o * 4 + h * 4;
    const float* xbase2 = xbase + (size_t)32 * CINC * LL;      // row +32
    const float* wbase = w + ((size_t)sr * CINC + si) * (OD * 8)
                           + (size_t)o * 8 + h * 4;
    const float* wbase2 = wbase + (size_t)32 * CINC * (OD * 8); // row +32

    // smem store offsets (within region), before stage/swizzle
    const uint32_t soff  = (uint32_t)(sr * 128 + si * 32 + h * 16);
    const uint32_t soff2 = soff + 32 * 128;

    // prefetch registers: 2 X strips-halves + 2 W strip-halves
    float4 xr0, xr1, wr0, wr1;

    // ---- prefetch chunk 0 ----
    xr0 = *reinterpret_cast<const float4*>(xbase);
    xr1 = *reinterpret_cast<const float4*>(xbase2);
    wr0 = *reinterpret_cast<const float4*>(wbase);
    wr1 = *reinterpret_cast<const float4*>(wbase2);

    for (int j = 0; j < NCHUNK; j++) {
        char* stgp = smem + (j & 1) * STAGE_SIZE;

        // ---- convert prefetched chunk j -> smem stage (tf32) ----
        cvt_sts(xr0, stgp + A_OFF + SWZ(soff));
        cvt_sts(xr1, stgp + A_OFF + SWZ(soff2));
        cvt_sts(wr0, stgp + B_OFF + SWZ(soff));
        cvt_sts(wr1, stgp + B_OFF + SWZ(soff2));
        __syncthreads();   // single barrier per chunk (double buffer)

        // ---- issue global prefetch for chunk j+1 (hides under MMA) ----
        if (j + 1 < NCHUNK) {
            const size_t xstep = (size_t)(j + 1) * 4 * LL;        // +4 i-rows
            const size_t wstep = (size_t)(j + 1) * 4 * (OD * 8);
            xr0 = *reinterpret_cast<const float4*>(xbase  + xstep);
            xr1 = *reinterpret_cast<const float4*>(xbase2 + xstep);
            wr0 = *reinterpret_cast<const float4*>(wbase  + wstep);
            wr1 = *reinterpret_cast<const float4*>(wbase2 + wstep);
        }

        // ---- MMA over 4 k8-steps of this chunk ----
        const uint32_t sstg = sb + (uint32_t)(j & 1) * STAGE_SIZE;
        #pragma unroll
        for (int kk = 0; kk < 4; kk++) {
            uint32_t a[4], b[2][4];

            {
                uint32_t row = (uint32_t)(m_base + (lid & 15));
                uint32_t off = SWZ(row * 128 + (uint32_t)kk * 32
                                   + (uint32_t)(lid >> 4) * 16);
                LDSM_X4(a, sstg + A_OFF + off);
            }
            #pragma unroll
            for (int nt2 = 0; nt2 < 2; nt2++) {
                uint32_t row = (uint32_t)(n_base + nt2 * 16 + (lid & 15));
                uint32_t off = SWZ(row * 128 + (uint32_t)kk * 32
                                   + (uint32_t)(lid >> 4) * 16);
                LDSM_X4(b[nt2], sstg + B_OFF + off);
            }

            #pragma unroll
            for (int nt = 0; nt < 4; nt++) {
                const int nt2 = nt >> 1;
                const int sel = nt & 1;
                MMA_TF32(acc[nt], a, b[nt2][sel], b[nt2][sel + 2]);
            }
        }
        // no trailing sync: next convert targets the other stage; the sync
        // above guarantees all reads of that stage (chunk j-1) are done.
    }

    // ---- epilogue: scale by 1/sqrt(64)=0.125, scatter ----
    const float scale = 0.125f;
    const int r    = lid >> 2;
    const int col2 = (lid & 3) * 2;
    #pragma unroll
    for (int nt = 0; nt < 4; nt++) {
        int b0 = bbase + m_base + r;
        int n0 = n_base + nt * 8 + col2;
        out[((size_t)b0 * NCOUT + n0) * OD + o]           = acc[nt][0] * scale;
        out[((size_t)b0 * NCOUT + n0 + 1) * OD + o]       = acc[nt][1] * scale;
        out[((size_t)(b0 + 8) * NCOUT + n0) * OD + o]     = acc[nt][2] * scale;
        out[((size_t)(b0 + 8) * NCOUT + n0 + 1) * OD + o] = acc[nt][3] * scale;
    }
}

extern "C" void kernel_launch(void* const* d_in, const int* in_sizes, int n_in,
                              void* d_out, int out_size) {
    const float* x = (const float*)d_in[0];
    const float* w = (const float*)d_in[1];
    float* out = (float*)d_out;

    dim3 grid(OD, 2);
    lc1d_tf32_kernel<<<grid, 256>>>(x, w, out);
}

// round 11
// speedup vs baseline: 1.2232x; 1.0046x over previous
#include <cuda_runtime.h>
#include <cuda_bf16.h>
#include <cstdint>

// LocallyConnected1d: out[b,c,o] = (1/8) * sum_{i<64,k<8} x[b,i,4o+k] * w[c,i,o,k]
// x: [128, 64, 1028] fp32, w: [1, 64, 64, 256, 8] fp32, out: [128, 64, 256] fp32
//
// Grid (256 o, 2 m-halves): each block = GEMM M=64(b), N=64(c), K=512 via
// mma.sync m16n8k8 tf32. KC=32 chunks, 2-stage 32KB SMEM, 4 CTAs/SM.
// R11: prefetch LDGs issued BEFORE the per-chunk barrier (hides LDG latency
// under barrier-wait + MMA), chunk loop unrolled x2, W uses default caching.

#define CINC  64
#define NCOUT 64
#define OD    256
#define LL    1028
#define M_BLK 64

#define KC      32              // K per chunk (32 tf32 = 128 B rows, SW128)
#define NCHUNK  16              // 512 / 32

// per-stage: A[64][32]u32 = 8 KB | B[64][32]u32 = 8 KB
#define A_OFF  0
#define B_OFF  8192
#define STAGE_SIZE 16384
#define SMEM_BYTES (2 * STAGE_SIZE)   // 32 KB static

// SW128 swizzle for 128-byte rows
#define SWZ(off) ((uint32_t)(off) ^ ((((uint32_t)(off)) >> 3) & 0x70u))

static __device__ __forceinline__ uint32_t smem_u32(const void* p) {
    uint32_t a;
    asm("{ .reg .u64 t; cvta.to.shared.u64 t, %1; cvt.u32.u64 %0, t; }"
        : "=r"(a) : "l"(p));
    return a;
}

static __device__ __forceinline__ uint32_t f2tf32(float f) {
    uint32_t r;
    asm("cvt.rna.tf32.f32 %0, %1;" : "=r"(r) : "f"(f));
    return r;
}

#define LDSM_X4(r, addr)                                                     \
    asm volatile("ldmatrix.sync.aligned.m8n8.x4.shared.b16 {%0,%1,%2,%3}, [%4];" \
        : "=r"((r)[0]), "=r"((r)[1]), "=r"((r)[2]), "=r"((r)[3]) : "r"(addr))

#define MMA_TF32(c, a, b0, b1)                                               \
    asm volatile("mma.sync.aligned.m16n8k8.row.col.f32.tf32.tf32.f32 "       \
        "{%0,%1,%2,%3}, {%4,%5,%6,%7}, {%8,%9}, {%0,%1,%2,%3};"              \
        : "+f"((c)[0]), "+f"((c)[1]), "+f"((c)[2]), "+f"((c)[3])             \
        : "r"((a)[0]), "r"((a)[1]), "r"((a)[2]), "r"((a)[3]),                \
          "r"(b0), "r"(b1))

// 4 f32 -> 4 tf32, one STS.128
static __device__ __forceinline__ void cvt_sts(float4 v, char* dst) {
    uint4 t;
    t.x = f2tf32(v.x);  t.y = f2tf32(v.y);
    t.z = f2tf32(v.z);  t.w = f2tf32(v.w);
    *reinterpret_cast<uint4*>(dst) = t;
}

__global__ __launch_bounds__(256, 4)
void lc1d_tf32_kernel(const float* __restrict__ x,
                      const float* __restrict__ w,
                      float* __restrict__ out)
{
    __shared__ char smem[SMEM_BYTES];
    const uint32_t sb = smem_u32(smem);

    const int o     = blockIdx.x;
    const int bbase = blockIdx.y * M_BLK;
    const int tid   = threadIdx.x;
    const int wid   = tid >> 5;
    const int lid   = tid & 31;

    // warp tile: 16(m=b) x 32(n=c); warp grid 4m x 2n
    const int m_base = (wid & 3) * 16;
    const int n_base = (wid >> 2) * 32;

    float acc[4][4];
    #pragma unroll
    for (int nt = 0; nt < 4; nt++)
        #pragma unroll
        for (int r = 0; r < 4; r++)
            acc[nt][r] = 0.0f;

    // pair-lane strip decomposition: pair p covers strip (row, i), halves h
    const int p  = tid >> 1;
    const int h  = tid & 1;
    const int si = p & 3;            // i-row within chunk (0..3)
    const int sr = (p >> 2) & 31;    // row 0..31; second strip at +32

    // per-thread gmem bases (strip starts, + h*16B)
    const float* xbase = x + ((size_t)(bbase + sr) * CINC + si) * LL
                           + (size_t)o * 4 + h * 4;
    const float* xbase2 = xbase + (size_t)32 * CINC * LL;      // row +32
    const float* wbase = w + ((size_t)sr * CINC + si) * (OD * 8)
                           + (size_t)o * 8 + h * 4;
    const float* wbase2 = wbase + (size_t)32 * CINC * (OD * 8); // row +32

    // smem store offsets (within region), before stage/swizzle
    const uint32_t soff  = (uint32_t)(sr * 128 + si * 32 + h * 16);
    const uint32_t soff2 = soff + 32 * 128;

    // prefetch registers
    float4 xr0, xr1, wr0, wr1;

    // ---- prefetch chunk 0 ----
    xr0 = *reinterpret_cast<const float4*>(xbase);
    xr1 = *reinterpret_cast<const float4*>(xbase2);
    wr0 = *reinterpret_cast<const float4*>(wbase);
    wr1 = *reinterpret_cast<const float4*>(wbase2);

    #pragma unroll 2
    for (int j = 0; j < NCHUNK; j++) {
        char* stgp = smem + (j & 1) * STAGE_SIZE;

        // ---- convert prefetched chunk j -> smem stage (tf32) ----
        cvt_sts(xr0, stgp + A_OFF + SWZ(soff));
        cvt_sts(xr1, stgp + A_OFF + SWZ(soff2));
        cvt_sts(wr0, stgp + B_OFF + SWZ(soff));
        cvt_sts(wr1, stgp + B_OFF + SWZ(soff2));

        // ---- issue global prefetch for chunk j+1 BEFORE the barrier:
        // its latency is covered by barrier-wait + the whole MMA loop ----
        if (j + 1 < NCHUNK) {
            const size_t xstep = (size_t)(j + 1) * 4 * LL;        // +4 i-rows
            const size_t wstep = (size_t)(j + 1) * 4 * (OD * 8);
            xr0 = *reinterpret_cast<const float4*>(xbase  + xstep);
            xr1 = *reinterpret_cast<const float4*>(xbase2 + xstep);
            wr0 = *reinterpret_cast<const float4*>(wbase  + wstep);
            wr1 = *reinterpret_cast<const float4*>(wbase2 + wstep);
        }

        __syncthreads();   // single barrier per chunk (double buffer)

        // ---- MMA over 4 k8-steps of this chunk ----
        const uint32_t sstg = sb + (uint32_t)(j & 1) * STAGE_SIZE;
        #pragma unroll
        for (int kk = 0; kk < 4; kk++) {
            uint32_t a[4], b[2][4];

            {
                uint32_t row = (uint32_t)(m_base + (lid & 15));
                uint32_t off = SWZ(row * 128 + (uint32_t)kk * 32
                                   + (uint32_t)(lid >> 4) * 16);
                LDSM_X4(a, sstg + A_OFF + off);
            }
            #pragma unroll
            for (int nt2 = 0; nt2 < 2; nt2++) {
                uint32_t row = (uint32_t)(n_base + nt2 * 16 + (lid & 15));
                uint32_t off = SWZ(row * 128 + (uint32_t)kk * 32
                                   + (uint32_t)(lid >> 4) * 16);
                LDSM_X4(b[nt2], sstg + B_OFF + off);
            }

            #pragma unroll
            for (int nt = 0; nt < 4; nt++) {
                const int nt2 = nt >> 1;
                const int sel = nt & 1;
                MMA_TF32(acc[nt], a, b[nt2][sel], b[nt2][sel + 2]);
            }
        }
        // no trailing sync: next convert targets the other stage; the sync
        // above guarantees all reads of that stage (chunk j-1) are done.
    }

    // ---- epilogue: scale by 1/sqrt(64)=0.125, scatter ----
    const float scale = 0.125f;
    const int r    = lid >> 2;
    const int col2 = (lid & 3) * 2;
    #pragma unroll
    for (int nt = 0; nt < 4; nt++) {
        int b0 = bbase + m_base + r;
        int n0 = n_base + nt * 8 + col2;
        out[((size_t)b0 * NCOUT + n0) * OD + o]           = acc[nt][0] * scale;
        out[((size_t)b0 * NCOUT + n0 + 1) * OD + o]       = acc[nt][1] * scale;
        out[((size_t)(b0 + 8) * NCOUT + n0) * OD + o]     = acc[nt][2] * scale;
        out[((size_t)(b0 + 8) * NCOUT + n0 + 1) * OD + o] = acc[nt][3] * scale;
    }
}

extern "C" void kernel_launch(void* const* d_in, const int* in_sizes, int n_in,
                              void* d_out, int out_size) {
    const float* x = (const float*)d_in[0];
    const float* w = (const float*)d_in[1];
    float* out = (float*)d_out;

    dim3 grid(OD, 2);
    lc1d_tf32_kernel<<<grid, 256>>>(x, w, out);
}

// round 12
// speedup vs baseline: 1.6489x; 1.3480x over previous
#include <cuda_runtime.h>
#include <cuda_bf16.h>
#include <cstdint>

// LocallyConnected1d: out[b,c,o] = (1/8) * sum_{i<64,k<8} x[b,i,4o+k] * w[c,i,o,k]
// x: [128, 64, 1028] fp32, w: [1, 64, 64, 256, 8] fp32, out: [128, 64, 256] fp32
//
// o-grouped blocks: block = (4 consecutive o) x (32-row b-quarter). One 128B
// gmem line per (b,i)/(c,i) strip serves all 4 o's (layout adjacency of o,k).
// 4 per-o tf32 GEMMs M=32,N=64,K=512 via mma.sync m16n8k8; 8 warps = 4 o x 2 n.
// Epilogue staged through SMEM so stores are STG.128 along o.

#define CINC  64
#define NCOUT 64
#define OD    256
#define LL    1028

#define NCHUNK  16              // K chunks of 32 (4 i-rows x 8 k)

// per-stage: 4 x A-tile[32][32]u32 (stride 4128 = 4KB + 32B stagger)
//          + 4 x B-tile[64][32]u32 (stride 8224 = 8KB + 32B stagger)
#define A_ST   4128
#define B_ST   8224
#define BREG   (4 * A_ST)                  // 16512
#define STAGE_SIZE (BREG + 4 * B_ST)       // 49408
#define SMEM_BYTES (2 * STAGE_SIZE)        // 98816

#define EPI_BF 260                          // epi b-stride in floats (1040 B)

// SW128 swizzle for 128-byte rows (proven R10/R11)
#define SWZ(off) ((uint32_t)(off) ^ ((((uint32_t)(off)) >> 3) & 0x70u))

static __device__ __forceinline__ uint32_t smem_u32(const void* p) {
    uint32_t a;
    asm("{ .reg .u64 t; cvta.to.shared.u64 t, %1; cvt.u32.u64 %0, t; }"
        : "=r"(a) : "l"(p));
    return a;
}

static __device__ __forceinline__ uint32_t f2tf32(float f) {
    uint32_t r;
    asm("cvt.rna.tf32.f32 %0, %1;" : "=r"(r) : "f"(f));
    return r;
}

static __device__ __forceinline__ uint4 cvt4(float4 v) {
    uint4 t;
    t.x = f2tf32(v.x);  t.y = f2tf32(v.y);
    t.z = f2tf32(v.z);  t.w = f2tf32(v.w);
    return t;
}

#define LDSM_X4(r, addr)                                                     \
    asm volatile("ldmatrix.sync.aligned.m8n8.x4.shared.b16 {%0,%1,%2,%3}, [%4];" \
        : "=r"((r)[0]), "=r"((r)[1]), "=r"((r)[2]), "=r"((r)[3]) : "r"(addr))

#define MMA_TF32(c, a, b0, b1)                                               \
    asm volatile("mma.sync.aligned.m16n8k8.row.col.f32.tf32.tf32.f32 "       \
        "{%0,%1,%2,%3}, {%4,%5,%6,%7}, {%8,%9}, {%0,%1,%2,%3};"              \
        : "+f"((c)[0]), "+f"((c)[1]), "+f"((c)[2]), "+f"((c)[3])             \
        : "r"((a)[0]), "r"((a)[1]), "r"((a)[2]), "r"((a)[3]),                \
          "r"(b0), "r"(b1))

__global__ __launch_bounds__(256, 2)
void lc1d_og4_kernel(const float* __restrict__ x,
                     const float* __restrict__ w,
                     float* __restrict__ out)
{
    extern __shared__ char smem[];
    const uint32_t sb = smem_u32(smem);

    const int o0    = blockIdx.x * 4;     // 64 o-groups
    const int bbase = blockIdx.y * 32;    // 4 b-quarters
    const int tid   = threadIdx.x;
    const int wid   = tid >> 5;
    const int lid   = tid & 31;

    const int o_w = wid >> 1;             // warp's o-tile (0..3)
    const int nh  = wid & 1;              // warp's n-half (0..1)

    float acc[2][4][4];
    #pragma unroll
    for (int mt = 0; mt < 2; mt++)
        #pragma unroll
        for (int nt = 0; nt < 4; nt++)
            #pragma unroll
            for (int r = 0; r < 4; r++)
                acc[mt][nt][r] = 0.0f;

    // ---- gather decomposition ----
    // X: strip (b, i) = 128B = x[b, i, 4*o0 .. 4*o0+31]; 8 lanes, lane m holds
    //    floats [4m, 4m+4). Lanes m>=5 unused (clamped load, no store).
    const int xm  = tid & 7;
    const int xms = xm > 4 ? 4 : xm;      // clamp: keeps og=63 strip in bounds
    const int bx  = tid >> 3;             // b row 0..31
    // W: strip (c, iw) = 128B = w[c, iw, o0..o0+3, 0..7]; per it (0..7):
    //    c = (it&1)*32 + (tid>>3), iw = it>>1; lane m holds floats [4m,4m+4).
    const int wm = tid & 7;
    const int pw = tid >> 3;

    const float* xrow = x + ((size_t)(bbase + bx) * CINC) * LL
                          + (size_t)o0 * 4 + xms * 4;
    // wsrc(it,j) = w + ((c*64 + j*4 + iw)*256 + o0)*8 + wm*4

    float4 xr[4], wr[8];

    // ---- prefetch chunk 0 ----
    #pragma unroll
    for (int it = 0; it < 4; it++)
        xr[it] = *reinterpret_cast<const float4*>(xrow + (size_t)it * LL);
    #pragma unroll
    for (int it = 0; it < 8; it++) {
        int cw = (it & 1) * 32 + pw;
        int iw = it >> 1;
        wr[it] = *reinterpret_cast<const float4*>(
            w + (((size_t)cw * CINC + iw) * OD + o0) * 8 + wm * 4);
    }

    for (int j = 0; j < NCHUNK; j++) {
        char* stgp = smem + (j & 1) * STAGE_SIZE;

        // ---- convert + scatter into 4 o-tiles ----
        #pragma unroll
        for (int it = 0; it < 4; it++) {
            uint4 t = cvt4(xr[it]);
            // lane m's floats land at window-pos 0..3 of o-tile m ...
            if (xm < 4)
                *reinterpret_cast<uint4*>(
                    stgp + xm * A_ST + SWZ((uint32_t)(bx * 128 + it * 32))) = t;
            // ... and at window-pos 4..7 of o-tile m-1
            if (xm >= 1 && xm <= 4)
                *reinterpret_cast<uint4*>(
                    stgp + (xm - 1) * A_ST
                         + SWZ((uint32_t)(bx * 128 + it * 32 + 16))) = t;
        }
        #pragma unroll
        for (int it = 0; it < 8; it++) {
            uint4 t = cvt4(wr[it]);
            int cw = (it & 1) * 32 + pw;
            int iw = it >> 1;
            *reinterpret_cast<uint4*>(
                stgp + BREG + (wm >> 1) * B_ST
                     + SWZ((uint32_t)(cw * 128 + iw * 32 + (wm & 1) * 16))) = t;
        }

        // ---- prefetch chunk j+1 before the barrier ----
        if (j + 1 < NCHUNK) {
            const size_t xstep = (size_t)(j + 1) * 4 * LL;
            #pragma unroll
            for (int it = 0; it < 4; it++)
                xr[it] = *reinterpret_cast<const float4*>(
                    xrow + xstep + (size_t)it * LL);
            #pragma unroll
            for (int it = 0; it < 8; it++) {
                int cw = (it & 1) * 32 + pw;
                int iw = (j + 1) * 4 + (it >> 1);
                wr[it] = *reinterpret_cast<const float4*>(
                    w + (((size_t)cw * CINC + iw) * OD + o0) * 8 + wm * 4);
            }
        }

        __syncthreads();   // single barrier per chunk (double buffer)

        // ---- MMA: warp = o-tile o_w, rows 0..31, cols nh*32..+32 ----
        const uint32_t astg = sb + (uint32_t)(j & 1) * STAGE_SIZE + o_w * A_ST;
        const uint32_t bstg = sb + (uint32_t)(j & 1) * STAGE_SIZE + BREG + o_w * B_ST;
        #pragma unroll
        for (int kk = 0; kk < 4; kk++) {
            uint32_t a[2][4], b[2][4];

            #pragma unroll
            for (int mt = 0; mt < 2; mt++) {
                uint32_t row = (uint32_t)(mt * 16 + (lid & 15));
                LDSM_X4(a[mt], astg + SWZ(row * 128 + (uint32_t)kk * 32
                                          + (uint32_t)(lid >> 4) * 16));
            }
            #pragma unroll
            for (int nt2 = 0; nt2 < 2; nt2++) {
                uint32_t row = (uint32_t)(nh * 32 + nt2 * 16 + (lid & 15));
                LDSM_X4(b[nt2], bstg + SWZ(row * 128 + (uint32_t)kk * 32
                                           + (uint32_t)(lid >> 4) * 16));
            }

            #pragma unroll
            for (int mt = 0; mt < 2; mt++) {
                #pragma unroll
                for (int nt = 0; nt < 4; nt++) {
                    const int nt2 = nt >> 1;
                    const int sel = nt & 1;
                    MMA_TF32(acc[mt][nt], a[mt],
                             b[nt2][sel], b[nt2][sel + 2]);
                }
            }
        }
        // no trailing sync (proven R10/R11 double-buffer argument)
    }

    // ---- epilogue: stage acc in SMEM as [b][c][o'] then STG.128 along o ----
    // (safe without a pre-sync: epi region = stage0; its last readers were
    //  chunk 14's MMAs, which every warp finished before chunk 15's barrier)
    float* epi = reinterpret_cast<float*>(smem);
    const float scale = 0.125f;
    {
        const int rr = lid >> 2;
        const int c2 = (lid & 3) * 2;
        #pragma unroll
        for (int mt = 0; mt < 2; mt++)
            #pragma unroll
            for (int nt = 0; nt < 4; nt++)
                #pragma unroll
                for (int r = 0; r < 4; r++) {
                    int bb = mt * 16 + rr + ((r >> 1) & 1) * 8;
                    int cc = nh * 32 + nt * 8 + c2 + (r & 1);
                    epi[bb * EPI_BF + cc * 4 + o_w] = acc[mt][nt][r] * scale;
                }
    }
    __syncthreads();

    #pragma unroll
    for (int r = 0; r < 8; r++) {
        int idx = tid + r * 256;          // 0..2047
        int bb  = idx >> 6;
        int cc  = idx & 63;
        float4 v = *reinterpret_cast<const float4*>(epi + bb * EPI_BF + cc * 4);
        *reinterpret_cast<float4*>(
            out + ((size_t)(bbase + bb) * NCOUT + cc) * OD + o0) = v;
    }
}

extern "C" void kernel_launch(void* const* d_in, const int* in_sizes, int n_in,
                              void* d_out, int out_size) {
    const float* x = (const float*)d_in[0];
    const float* w = (const float*)d_in[1];
    float* out = (float*)d_out;

    static int configured = 0;
    if (!configured) {
        cudaFuncSetAttribute(lc1d_og4_kernel,
                             cudaFuncAttributeMaxDynamicSharedMemorySize, SMEM_BYTES);
        configured = 1;
    }
    dim3 grid(OD / 4, 4);
    lc1d_og4_kernel<<<grid, 256, SMEM_BYTES>>>(x, w, out);
}

// round 13
// speedup vs baseline: 1.7319x; 1.0504x over previous
#include <cuda_runtime.h>
#include <cuda_bf16.h>
#include <cstdint>

// LocallyConnected1d: out[b,c,o] = (1/8) * sum_{i<64,k<8} x[b,i,4o+k] * w[c,i,o,k]
// x: [128, 64, 1028] fp32, w: [1, 64, 64, 256, 8] fp32, out: [128, 64, 256] fp32
//
// o-grouped blocks (R12 layout) + R13 strength reduction: precomputed swizzle
// bases (XOR identity), pointer-increment gmem addressing, conflict-free epi.

#define CINC  64
#define NCOUT 64
#define OD    256
#define LL    1028

#define NCHUNK  16              // K chunks of 32 (4 i-rows x 8 k)

#define A_ST   4128             // A-tile stride: 4KB + 32B stagger
#define B_ST   8224             // B-tile stride: 8KB + 32B stagger
#define BREG   (4 * A_ST)                  // 16512
#define STAGE_SIZE (BREG + 4 * B_ST)       // 49408
#define SMEM_BYTES (2 * STAGE_SIZE)        // 98816

#define EPI_BF 268              // stride 67 banks: epi STS conflict-free

static __device__ __forceinline__ uint32_t smem_u32(const void* p) {
    uint32_t a;
    asm("{ .reg .u64 t; cvta.to.shared.u64 t, %1; cvt.u32.u64 %0, t; }"
        : "=r"(a) : "l"(p));
    return a;
}

static __device__ __forceinline__ uint32_t f2tf32(float f) {
    uint32_t r;
    asm("cvt.rna.tf32.f32 %0, %1;" : "=r"(r) : "f"(f));
    return r;
}

static __device__ __forceinline__ uint4 cvt4(float4 v) {
    uint4 t;
    t.x = f2tf32(v.x);  t.y = f2tf32(v.y);
    t.z = f2tf32(v.z);  t.w = f2tf32(v.w);
    return t;
}

#define LDSM_X4(r, addr)                                                     \
    asm volatile("ldmatrix.sync.aligned.m8n8.x4.shared.b16 {%0,%1,%2,%3}, [%4];" \
        : "=r"((r)[0]), "=r"((r)[1]), "=r"((r)[2]), "=r"((r)[3]) : "r"(addr))

#define MMA_TF32(c, a, b0, b1)                                               \
    asm volatile("mma.sync.aligned.m16n8k8.row.col.f32.tf32.tf32.f32 "       \
        "{%0,%1,%2,%3}, {%4,%5,%6,%7}, {%8,%9}, {%0,%1,%2,%3};"              \
        : "+f"((c)[0]), "+f"((c)[1]), "+f"((c)[2]), "+f"((c)[3])             \
        : "r"((a)[0]), "r"((a)[1]), "r"((a)[2]), "r"((a)[3]),                \
          "r"(b0), "r"(b1))

__global__ __launch_bounds__(256, 2)
void lc1d_og4_kernel(const float* __restrict__ x,
                     const float* __restrict__ w,
                     float* __restrict__ out)
{
    extern __shared__ char smem[];
    const uint32_t sb = smem_u32(smem);

    const int o0    = blockIdx.x * 4;     // 64 o-groups
    const int bbase = blockIdx.y * 32;    // 4 b-quarters
    const int tid   = threadIdx.x;
    const int wid   = tid >> 5;
    const int lid   = tid & 31;

    const int o_w = wid >> 1;             // warp's o-tile (0..3)
    const int nh  = wid & 1;              // warp's n-half (0..1)

    float acc[2][4][4];
    #pragma unroll
    for (int mt = 0; mt < 2; mt++)
        #pragma unroll
        for (int nt = 0; nt < 4; nt++)
            #pragma unroll
            for (int r = 0; r < 4; r++)
                acc[mt][nt][r] = 0.0f;

    // ---- gather decomposition (R12) ----
    const int xm  = tid & 7;
    const int xms = xm > 4 ? 4 : xm;      // clamp keeps og=63 strip in bounds
    const int bx  = tid >> 3;
    const int wm  = tid & 7;
    const int pw  = tid >> 3;

    // gmem pointers (advanced by constant stride per chunk)
    const float* xptr = x + ((size_t)(bbase + bx) * CINC) * LL
                          + (size_t)o0 * 4 + xms * 4;
    const float* wp0  = w + (((size_t)pw * CINC) * OD + o0) * 8 + wm * 4;
    const float* wp1  = wp0 + (size_t)32 * CINC * OD * 8;

    // ---- store-side precomputed offsets (u32, from smem base) ----
    const uint32_t xs1 = (uint32_t)(xm * A_ST + bx * 128);
    const uint32_t xs2 = (uint32_t)((xm - 1) * A_ST + bx * 128);  // used iff xm>=1
    const uint32_t kx  = (uint32_t)((bx & 7) << 4);
    const uint32_t kx2 = kx ^ 16u;
    const uint32_t wsb = (uint32_t)(BREG + (wm >> 1) * B_ST + pw * 128);
    const uint32_t kw  = ((uint32_t)((pw & 7) << 4)) ^ ((uint32_t)((wm & 1) << 4));

    // ---- ldsm precomputed bases ----
    const uint32_t lr = (uint32_t)(lid & 15);
    const uint32_t sk = ((uint32_t)(lid >> 4) << 4) ^ ((uint32_t)(lid & 7) << 4);
    const uint32_t baseA0 = sb + (uint32_t)(o_w * A_ST) + lr * 128;
    const uint32_t baseA1 = baseA0 + 16 * 128;
    const uint32_t baseB0 = sb + (uint32_t)(BREG + o_w * B_ST)
                               + (uint32_t)(nh * 32 + lr) * 128;
    const uint32_t baseB1 = baseB0 + 16 * 128;

    float4 xr[4], wr[8];

    // ---- prefetch chunk 0 ----
    #pragma unroll
    for (int it = 0; it < 4; it++)
        xr[it] = *reinterpret_cast<const float4*>(xptr + (size_t)it * LL);
    #pragma unroll
    for (int it = 0; it < 8; it++)
        wr[it] = *reinterpret_cast<const float4*>(
            ((it & 1) ? wp1 : wp0) + (size_t)(it >> 1) * (OD * 8));

    #pragma unroll 2
    for (int j = 0; j < NCHUNK; j++) {
        const uint32_t stg = (uint32_t)(j & 1) * STAGE_SIZE;
        char* const stgp = smem + stg;

        // ---- convert + scatter into 4 o-tiles ----
        #pragma unroll
        for (int it = 0; it < 4; it++) {
            uint4 t = cvt4(xr[it]);
            if (xm < 4)
                *reinterpret_cast<uint4*>(
                    stgp + xs1 + (kx ^ (uint32_t)(it * 32))) = t;
            if (xm >= 1 && xm <= 4)
                *reinterpret_cast<uint4*>(
                    stgp + xs2 + (kx2 ^ (uint32_t)(it * 32))) = t;
        }
        #pragma unroll
        for (int it = 0; it < 8; it++) {
            uint4 t = cvt4(wr[it]);
            *reinterpret_cast<uint4*>(
                stgp + wsb + (uint32_t)((it & 1) * 4096)
                     + (kw ^ (uint32_t)((it >> 1) * 32))) = t;
        }

        // ---- prefetch chunk j+1 before the barrier ----
        if (j + 1 < NCHUNK) {
            xptr += 4 * LL;
            wp0  += 4 * (OD * 8);
            wp1  += 4 * (OD * 8);
            #pragma unroll
            for (int it = 0; it < 4; it++)
                xr[it] = *reinterpret_cast<const float4*>(xptr + (size_t)it * LL);
            #pragma unroll
            for (int it = 0; it < 8; it++)
                wr[it] = *reinterpret_cast<const float4*>(
                    ((it & 1) ? wp1 : wp0) + (size_t)(it >> 1) * (OD * 8));
        }

        __syncthreads();   // single barrier per chunk (double buffer)

        // ---- MMA: 4 k8-steps, precomputed bases + 1 LOP3 per ldsm ----
        #pragma unroll
        for (int kk = 0; kk < 4; kk++) {
            const uint32_t ko = sk ^ (uint32_t)(kk * 32);
            uint32_t a[2][4], b[2][4];
            LDSM_X4(a[0], baseA0 + stg + ko);
            LDSM_X4(a[1], baseA1 + stg + ko);
            LDSM_X4(b[0], baseB0 + stg + ko);
            LDSM_X4(b[1], baseB1 + stg + ko);

            #pragma unroll
            for (int mt = 0; mt < 2; mt++) {
                #pragma unroll
                for (int nt = 0; nt < 4; nt++) {
                    const int nt2 = nt >> 1;
                    const int sel = nt & 1;
                    MMA_TF32(acc[mt][nt], a[mt],
                             b[nt2][sel], b[nt2][sel + 2]);
                }
            }
        }
        // no trailing sync (double-buffer argument, proven R10-R12)
    }

    // ---- epilogue: stage acc in SMEM [b][c][o'] (EPI_BF=268, conflict-free),
    //      then STG.128 along o ----
    float* epi = reinterpret_cast<float*>(smem);
    const float scale = 0.125f;
    {
        const int rr = lid >> 2;
        const int c2 = (lid & 3) * 2;
        #pragma unroll
        for (int mt = 0; mt < 2; mt++)
            #pragma unroll
            for (int nt = 0; nt < 4; nt++)
                #pragma unroll
                for (int r = 0; r < 4; r++) {
                    int bb = mt * 16 + rr + ((r >> 1) & 1) * 8;
                    int cc = nh * 32 + nt * 8 + c2 + (r & 1);
                    epi[bb * EPI_BF + cc * 4 + o_w] = acc[mt][nt][r] * scale;
                }
    }
    __syncthreads();

    #pragma unroll
    for (int r = 0; r < 8; r++) {
        int idx = tid + r * 256;          // 0..2047
        int bb  = idx >> 6;
        int cc  = idx & 63;
        float4 v = *reinterpret_cast<const float4*>(epi + bb * EPI_BF + cc * 4);
        *reinterpret_cast<float4*>(
            out + ((size_t)(bbase + bb) * NCOUT + cc) * OD + o0) = v;
    }
}

extern "C" void kernel_launch(void* const* d_in, const int* in_sizes, int n_in,
                              void* d_out, int out_size) {
    const float* x = (const float*)d_in[0];
    const float* w = (const float*)d_in[1];
    float* out = (float*)d_out;

    static int configured = 0;
    if (!configured) {
        cudaFuncSetAttribute(lc1d_og4_kernel,
                             cudaFuncAttributeMaxDynamicSharedMemorySize, SMEM_BYTES);
        configured = 1;
    }
    dim3 grid(OD / 4, 4);
    lc1d_og4_kernel<<<grid, 256, SMEM_BYTES>>>(x, w, out);
}